// round 17
// baseline (speedup 1.0000x reference)
#include <cuda_runtime.h>

#define BB 8
#define DD 16
#define HH 384
#define WW 384
#define HW (HH * WW)            /* 147456 */
#define NBV (DD * HW)           /* 2359296 */
#define NT (BB * NBV)           /* 18874368 voxels */
#define NW (NT / 32)            /* 589824 bit-words */
#define ROWS (BB * DD * HH)     /* 49152 rows of W=384 */
#define WPR 12                  /* words per row */
#define SLOTW 16                /* run slots per word (max starts per word) */
#define NR (NW * SLOTW)         /* 9437184 run slots (< 2^24) */

#define STRONGBIT (1 << 24)     /* set on keys of runs WITHOUT strong voxels */
#define IDXMASK (STRONGBIT - 1)

// ---- scratch (__device__ globals; no runtime allocation) ----
__device__ int g_parent[NR];          // stores KEYS (index | maybe STRONGBIT)
__device__ int g_cnt[NR];
__device__ unsigned g_weak[NW];
__device__ unsigned g_hyst[NW];
__device__ unsigned g_mask2[NW];
__device__ unsigned char g_nstart[NW]; // # run starts in each word

// findRoot with path halving; returns the ROOT KEY.
__device__ __forceinline__ int findRoot(int* P, int i) {
    int k = P[i];
    int ki = k & IDXMASK;
    int kk = P[ki];
    while (k != kk) {
        P[i] = kk;
        i = ki;
        k = kk;
        ki = k & IDXMASK;
        kk = P[ki];
    }
    return k;
}

__device__ __forceinline__ void unite(int* P, int ai, int bi) {
    int ak = findRoot(P, ai);
    int bk = findRoot(P, bi);
    while (ak != bk) {
        if (ak > bk) { int t = ak; ak = bk; bk = t; }
        int bidx = bk & IDXMASK;
        int old = atomicMin(&P[bidx], ak);
        if (old == bk) return;
        bk = findRoot(P, old & IDXMASK);
    }
}

__device__ __forceinline__ unsigned lemask(int b) { return (2u << b) - 1u; }

// run-id of the run covering bit b of word wi. sC = starts in wi.
// Continuation (no start <= b in this word): walk back to nearest word with a
// start (exists: runs never span rows, and a continuation's start is in-row).
__device__ __forceinline__ int runIdOf(unsigned sC, int b, int wi) {
    unsigned below = sC & lemask(b);
    if (below) return wi * SLOTW + __popc(below) - 1;
    int j = wi - 1;
    while (!g_nstart[j]) j--;
    return j * SLOTW + g_nstart[j] - 1;
}

// K1 (thread/word): thresholds from float4 loads; masks + nstart; init parent
// keys for runs starting here, resolving the strong flag inline (in-word
// segment test + rare forward walk for word-spanning runs).
__global__ void k1_threshold(const float* __restrict__ in) {
    int wi = blockIdx.x * blockDim.x + threadIdx.x;
    if (wi >= NW) return;
    int wd = wi % WPR;
    const float4* ip = reinterpret_cast<const float4*>(in) + wi * 8;
    unsigned w = 0, s = 0;
#pragma unroll
    for (int k = 0; k < 8; k++) {
        float4 v = ip[k];
        w |= ((unsigned)(v.x >= 0.8f))  << (4 * k);
        w |= ((unsigned)(v.y >= 0.8f))  << (4 * k + 1);
        w |= ((unsigned)(v.z >= 0.8f))  << (4 * k + 2);
        w |= ((unsigned)(v.w >= 0.8f))  << (4 * k + 3);
        s |= ((unsigned)(v.x >= 0.92f)) << (4 * k);
        s |= ((unsigned)(v.y >= 0.92f)) << (4 * k + 1);
        s |= ((unsigned)(v.z >= 0.92f)) << (4 * k + 2);
        s |= ((unsigned)(v.w >= 0.92f)) << (4 * k + 3);
    }
    unsigned carry = 0;
    if (wd) carry = (unsigned)(in[wi * 32 - 1] >= 0.8f);
    unsigned sC = w & ~((w << 1) | carry);
    g_weak[wi] = w;
    g_nstart[wi] = (unsigned char)__popc(sC);
    int nbase = wi * SLOTW;
    int rowendVox = (wi - wd + WPR) * 32;
    unsigned st = sC;
    int k = 0;
    while (st) {
        int b = __ffs(st) - 1; st &= st - 1;
        unsigned x = w >> b;
        int len = (x == 0xffffffffu) ? 32 : (__ffs(~x) - 1);
        unsigned seg = ((len == 32) ? 0xffffffffu : ((1u << len) - 1u)) << b;
        bool strong = (s & seg) != 0;
        if (!strong && b + len == 32) {
            // run continues into following word(s) of this row: walk floats
            int q = wi * 32 + 32;
            while (q < rowendVox) {
                float f = in[q];
                if (f < 0.8f) break;
                if (f >= 0.92f) { strong = true; break; }
                q++;
            }
        }
        int ri = nbase + k;
        g_parent[ri] = strong ? ri : (ri | STRONGBIT);
        k++;
    }
}

// K2/K5b (thread/word): one unite per overlap segment with h-1 / z-1 rows
template <bool SECOND>
__global__ void k2_merge() {
    int wi = blockIdx.x * blockDim.x + threadIdx.x;
    if (wi >= NW) return;
    int row = wi / WPR, wd = wi - row * WPR;
    const unsigned* __restrict__ M = SECOND ? g_mask2 : g_weak;
    unsigned cur = M[wi];
    if (!cur) return;
    int h = row % HH, z = (row / HH) % DD;
    bool hasH = (h > 0), hasD = (z > 0);
    if (!hasH && !hasD) return;
    unsigned prevC = wd ? M[wi - 1] : 0;
    unsigned sC = cur & ~((cur << 1) | (prevC >> 31));
    if (hasH) {
        unsigned nh = M[wi - WPR];
        unsigned ov = cur & nh;
        if (ov) {
            unsigned prevH = wd ? M[wi - 1 - WPR] : 0;
            unsigned sH = nh & ~((nh << 1) | (prevH >> 31));
            unsigned so = ov & ~((ov << 1) | ((prevC & prevH) >> 31));
            while (so) {
                int b = __ffs(so) - 1; so &= so - 1;
                int ra = runIdOf(sC, b, wi);
                int rb = runIdOf(sH, b, wi - WPR);
                unite(g_parent, ra, rb);
            }
        }
    }
    if (hasD) {
        unsigned nd = M[wi - WPR * HH];
        unsigned ov = cur & nd;
        if (ov) {
            unsigned prevD = wd ? M[wi - 1 - WPR * HH] : 0;
            unsigned sD = nd & ~((nd << 1) | (prevD >> 31));
            unsigned so = ov & ~((ov << 1) | ((prevC & prevD) >> 31));
            while (so) {
                int b = __ffs(so) - 1; so &= so - 1;
                int ra = runIdOf(sC, b, wi);
                int rb = runIdOf(sD, b, wi - WPR * HH);
                unite(g_parent, ra, rb);
            }
        }
    }
}

// K4 (thread/word): hysteresis — kept iff root key lacks STRONGBIT
__global__ void k4_hyst() {
    int wi = blockIdx.x * blockDim.x + threadIdx.x;
    if (wi >= NW) return;
    unsigned cur = g_weak[wi];
    unsigned hy = 0;
    if (cur) {
        int wd = wi % WPR;
        unsigned prevC = wd ? g_weak[wi - 1] : 0;
        unsigned sC = cur & ~((cur << 1) | (prevC >> 31));
        unsigned m = cur;
        while (m) {
            int b = __ffs(m) - 1;
            unsigned x = m >> b;
            int len = (x == 0xffffffffu) ? 32 : (__ffs(~x) - 1);
            unsigned seg = ((len == 32) ? 0xffffffffu : ((1u << len) - 1u)) << b;
            int ri = runIdOf(sC, b, wi);
            int rk = findRoot(g_parent, ri);
            if (!(rk & STRONGBIT)) hy |= seg;
            m &= ~seg;
        }
    }
    g_hyst[wi] = hy;
}

// erosion-of-dilation along z for word wj (z = its plane)
__device__ __forceinline__ unsigned ero_at(int wj, int z) {
    const int ZOFF = WPR * HH;
    unsigned h0  = g_hyst[wj];
    unsigned hm1 = (z >= 1)      ? g_hyst[wj - ZOFF]     : 0u;
    unsigned hm2 = (z >= 2)      ? g_hyst[wj - 2 * ZOFF] : 0u;
    unsigned hp1 = (z <= DD - 2) ? g_hyst[wj + ZOFF]     : 0u;
    unsigned hp2 = (z <= DD - 3) ? g_hyst[wj + 2 * ZOFF] : 0u;
    unsigned dilm = hm2 | hm1 | h0;
    unsigned dil0 = hm1 | h0 | hp1;
    unsigned dilp = h0 | hp1 | hp2;
    return (z ? dilm : 0xffffffffu) & dil0 &
           ((z < DD - 1) ? dilp : 0xffffffffu);
}

// K5a (thread/word): z-closing + nstart + pass-2 parent/cnt init
__global__ void k5a_close() {
    int wi = blockIdx.x * blockDim.x + threadIdx.x;
    if (wi >= NW) return;
    int row = wi / WPR, wd = wi - row * WPR;
    int z = (row / HH) % DD;
    unsigned my2 = ero_at(wi, z);
    unsigned carry = wd ? (ero_at(wi - 1, z) >> 31) : 0;
    unsigned sC = my2 & ~((my2 << 1) | carry);
    g_mask2[wi] = my2;
    int ns = __popc(sC);
    g_nstart[wi] = (unsigned char)ns;
    int nbase = wi * SLOTW;
    for (int k = 0; k < ns; k++) {
        g_parent[nbase + k] = nbase + k;
        g_cnt[nbase + k] = 0;
    }
}

// K5c (thread/word): per-word-piece length accumulation at component root
__global__ void k5c_count() {
    int wi = blockIdx.x * blockDim.x + threadIdx.x;
    if (wi >= NW) return;
    unsigned cur = g_mask2[wi];
    if (!cur) return;
    int wd = wi % WPR;
    unsigned prevC = wd ? g_mask2[wi - 1] : 0;
    unsigned sC = cur & ~((cur << 1) | (prevC >> 31));
    unsigned m = cur;
    while (m) {
        int b = __ffs(m) - 1;
        unsigned x = m >> b;
        int len = (x == 0xffffffffu) ? 32 : (__ffs(~x) - 1);
        unsigned seg = ((len == 32) ? 0xffffffffu : ((1u << len) - 1u)) << b;
        int ri = runIdOf(sC, b, wi);
        int rk = findRoot(g_parent, ri);
        atomicAdd(&g_cnt[rk & IDXMASK], len);
        m &= ~seg;
    }
}

// K6 (thread/word): keep mask per word, float4 stores
__global__ void k6_final(float* __restrict__ out) {
    int wi = blockIdx.x * blockDim.x + threadIdx.x;
    if (wi >= NW) return;
    unsigned cur = g_mask2[wi];
    unsigned keep = 0;
    if (cur) {
        int wd = wi % WPR;
        unsigned prevC = wd ? g_mask2[wi - 1] : 0;
        unsigned sC = cur & ~((cur << 1) | (prevC >> 31));
        unsigned m = cur;
        while (m) {
            int b = __ffs(m) - 1;
            unsigned x = m >> b;
            int len = (x == 0xffffffffu) ? 32 : (__ffs(~x) - 1);
            unsigned seg = ((len == 32) ? 0xffffffffu : ((1u << len) - 1u)) << b;
            int ri = runIdOf(sC, b, wi);
            int rk = findRoot(g_parent, ri);
            if (g_cnt[rk & IDXMASK] >= 20) keep |= seg;
            m &= ~seg;
        }
    }
    float4* out4 = reinterpret_cast<float4*>(out) + wi * 8;
#pragma unroll
    for (int k = 0; k < 8; k++) {
        out4[k] = make_float4(
            ((keep >> (4 * k + 0)) & 1) ? 1.0f : 0.0f,
            ((keep >> (4 * k + 1)) & 1) ? 1.0f : 0.0f,
            ((keep >> (4 * k + 2)) & 1) ? 1.0f : 0.0f,
            ((keep >> (4 * k + 3)) & 1) ? 1.0f : 0.0f);
    }
}

extern "C" void kernel_launch(void* const* d_in, const int* in_sizes, int n_in,
                              void* d_out, int out_size) {
    const float* in = (const float*)d_in[0];
    float* out = (float*)d_out;

    const int TPB = 256;
    const int GRID_W = (NW + TPB - 1) / TPB;   // 2304 blocks, thread per word

    k1_threshold<<<GRID_W, TPB>>>(in);
    k2_merge<false><<<GRID_W, TPB>>>();
    k4_hyst<<<GRID_W, TPB>>>();
    k5a_close<<<GRID_W, TPB>>>();
    k2_merge<true><<<GRID_W, TPB>>>();
    k5c_count<<<GRID_W, TPB>>>();
    k6_final<<<GRID_W, TPB>>>(out);
}